// round 8
// baseline (speedup 1.0000x reference)
#include <cuda_runtime.h>
#include <math.h>

#define HH 512
#define WW 512
#define NB 64
#define PD 15
#define RB 64                 // rows per band (per CTA)
#define BANDS (HH / RB)       // 8
#define GG 8                  // rows per smem group
#define NGROUPS (RB / GG)     // 8
#define NTH 512
#define SBW 560               // swizzled row width (>= scol(542)+1 = 559)
#define NBLOCKS (BANDS * NB)  // 512

__device__ __forceinline__ int scol(int c) { return c + (c >> 5); }

__device__ float g_part[NB * BANDS * 2];
__device__ unsigned int g_count = 0;

__global__ __launch_bounds__(NTH, 4)
void fused_kernel(const float* __restrict__ pred, const float* __restrict__ mask,
                  float* __restrict__ out) {
    __shared__ float buf[2][GG][SBW];
    __shared__ float s_i[16], s_u[16];
    __shared__ bool amLast;

    const int t    = threadIdx.x;           // = column for phase A
    const int band = blockIdx.x;
    const int b    = blockIdx.y;
    const int r0   = band * RB;
    const float* mb = mask + (size_t)b * HH * WW;
    const float* pb = pred + (size_t)b * HH * WW;

    // zero both buffers once (halo regions stay zero thereafter)
    #pragma unroll
    for (int i = t; i < 2 * GG * SBW; i += NTH) ((float*)buf)[i] = 0.f;

    // vertical running-sum init: 30 rows [r0-15, r0+14], 4-way ILP tree.
    // Tree covers rows 0..27 of the window (28 rows, j<28!), leftovers 28,29.
    float s;
    {
        float a0 = 0.f, a1 = 0.f, a2 = 0.f, a3 = 0.f;
        #pragma unroll
        for (int j = 0; j < 28; j += 4) {
            int g0 = r0 - PD + j;
            if ((unsigned)(g0 + 0) < HH) a0 += mb[(g0 + 0) * WW + t];
            if ((unsigned)(g0 + 1) < HH) a1 += mb[(g0 + 1) * WW + t];
            if ((unsigned)(g0 + 2) < HH) a2 += mb[(g0 + 2) * WW + t];
            if ((unsigned)(g0 + 3) < HH) a3 += mb[(g0 + 3) * WW + t];
        }
        int g28 = r0 - PD + 28, g29 = r0 - PD + 29;
        if ((unsigned)g28 < HH) a0 += mb[g28 * WW + t];
        if ((unsigned)g29 < HH) a1 += mb[g29 * WW + t];
        s = (a0 + a1) + (a2 + a3);
    }

    // zeroing must complete before any staged interior write
    __syncthreads();

    // ---- prologue: phase A for group 0 into buf[0] ----
    #pragma unroll
    for (int rr = 0; rr < GG; ++rr) {
        int gr = r0 + rr;
        float lead = (gr + PD < HH) ? mb[(gr + PD) * WW + t] : 0.f;
        s += lead;
        buf[0][rr][scol(t + PD)] = s;
        float trail = (gr - PD >= 0) ? mb[(gr - PD) * WW + t] : 0.f;
        s -= trail;
    }
    __syncthreads();

    const float inv = 1.0f / 961.0f;
    float fi = 0.f, fu = 0.f;

    // phase-B mapping: 64 threads per row, 8 cols per thread
    const int rg = t >> 6;                  // 0..7 row-in-group
    const int c0 = (t & 63) * 8;            // 8-column chunk

    for (int g = 0; g < NGROUPS; ++g) {
        // ---- phase A for group g+1 into buf[(g+1)&1] (overlaps phase B) ----
        if (g + 1 < NGROUPS) {
            const int rbase = r0 + (g + 1) * GG;
            float* bw = &buf[(g + 1) & 1][0][0];
            #pragma unroll
            for (int rr = 0; rr < GG; ++rr) {
                int gr = rbase + rr;
                float lead = (gr + PD < HH) ? mb[(gr + PD) * WW + t] : 0.f;
                s += lead;
                bw[rr * SBW + scol(t + PD)] = s;
                float trail = (gr - PD >= 0) ? mb[(gr - PD) * WW + t] : 0.f;
                s -= trail;
            }
        }

        // ---- phase B for group g from buf[g&1] ----
        {
            const int grB = r0 + g * GG + rg;
            const float* br = &buf[g & 1][rg][0];
            const float* mrow = mb + grB * WW + c0;
            const float* prow = pb + grB * WW + c0;

            // 31-tap window init with 4-way ILP tree (28 in tree + 3 leftovers)
            float hs;
            {
                float a0 = 0.f, a1 = 0.f, a2 = 0.f, a3 = 0.f;
                #pragma unroll
                for (int j = 0; j < 28; j += 4) {
                    a0 += br[scol(c0 + j + 0)];
                    a1 += br[scol(c0 + j + 1)];
                    a2 += br[scol(c0 + j + 2)];
                    a3 += br[scol(c0 + j + 3)];
                }
                a0 += br[scol(c0 + 28)];
                a1 += br[scol(c0 + 29)];
                a2 += br[scol(c0 + 30)];
                hs = (a0 + a1) + (a2 + a3);
            }

            // two 4-column register batches (keeps live regs low)
            #pragma unroll
            for (int h = 0; h < 2; ++h) {
                float4 m4 = *reinterpret_cast<const float4*>(mrow + h * 4);
                float4 p4 = *reinterpret_cast<const float4*>(prow + h * 4);
                float mk[4] = {m4.x, m4.y, m4.z, m4.w};
                float pr[4] = {p4.x, p4.y, p4.z, p4.w};
                #pragma unroll
                for (int q = 0; q < 4; ++q) {
                    int c = c0 + h * 4 + q;
                    float avg  = hs * inv;
                    float weit = fmaf(5.f, fabsf(avg - mk[q]), 1.f);
                    float p    = __frcp_rn(1.f + __expf(-pr[q]));
                    fi = fmaf(p * mk[q], weit, fi);
                    fu = fmaf(p + mk[q], weit, fu);
                    hs += br[scol(c + 31)] - br[scol(c)];
                }
            }
        }
        __syncthreads();
    }

    // ---- block reduce 512 -> 1 ----
    #pragma unroll
    for (int o = 16; o; o >>= 1) {
        fi += __shfl_down_sync(0xffffffffu, fi, o);
        fu += __shfl_down_sync(0xffffffffu, fu, o);
    }
    int wid = t >> 5, lane = t & 31;
    if (lane == 0) { s_i[wid] = fi; s_u[wid] = fu; }
    __syncthreads();
    if (wid == 0) {
        float ti = (lane < 16) ? s_i[lane] : 0.f;
        float tu = (lane < 16) ? s_u[lane] : 0.f;
        #pragma unroll
        for (int o = 8; o; o >>= 1) {
            ti += __shfl_down_sync(0xffffffffu, ti, o);
            tu += __shfl_down_sync(0xffffffffu, tu, o);
        }
        if (lane == 0) {
            g_part[(b * BANDS + band) * 2 + 0] = ti;
            g_part[(b * BANDS + band) * 2 + 1] = tu;
            __threadfence();
            unsigned int done = atomicAdd(&g_count, 1u);
            amLast = (done == NBLOCKS - 1);
        }
    }
    __syncthreads();

    // ---- last CTA: finalize ----
    if (amLast) {
        double w = 0.0;
        if (t < NB) {
            double it = 0.0, un = 0.0;
            #pragma unroll
            for (int p = 0; p < BANDS; ++p) {
                it += (double)g_part[(t * BANDS + p) * 2 + 0];
                un += (double)g_part[(t * BANDS + p) * 2 + 1];
            }
            w = 1.0 - (2.0 * it + 0.5) / (un + 0.5);
        }
        #pragma unroll
        for (int o = 16; o; o >>= 1) w += __shfl_down_sync(0xffffffffu, w, o);
        __shared__ double sh[2];
        if (t < 64 && (t & 31) == 0) sh[t >> 5] = w;
        __syncthreads();
        if (t == 0) {
            out[0] = (float)((sh[0] + sh[1]) / (double)NB);
            g_count = 0;   // reset for next graph replay
        }
    }
}

extern "C" void kernel_launch(void* const* d_in, const int* in_sizes, int n_in,
                              void* d_out, int out_size) {
    const float* pred = (const float*)d_in[0];
    const float* mask = (const float*)d_in[1];
    float* out = (float*)d_out;

    fused_kernel<<<dim3(BANDS, NB), NTH>>>(pred, mask, out);
}